// round 14
// baseline (speedup 1.0000x reference)
#include <cuda_runtime.h>
#include <math.h>

#define B_     8
#define N_     10000
#define D_     16
#define E_     320000
#define EH_    32
#define EOUT_  30
#define NOUT_  64
#define BN_    (B_ * N_)
#define ZGRID_ 512

typedef unsigned long long ull;

// ---------------- packed constant block (one D2D memcpy) ----------------
struct Pack {
    float W1[35 * EH_];      // layer-1 weights
    float b1[EH_];
    float W2t[EOUT_ * EH_];  // transposed layer-2 [30][32]
    float b2[EOUT_];
    float Wn[EOUT_ * NOUT_];
    float bn[NOUT_];
    float wind[4];           // wm0, wm1, ws0, ws1
    float norm[4];           // mean0, mean1, rstd0, rstd1
};
__constant__ Pack c_p;
__device__ Pack g_pack;     // staged by prep_kernel

// ---------------- device scratch ----------------
__device__ double g_part[ZGRID_ * 4];
__device__ unsigned g_counter = 0;
__device__ __align__(16) float4 g_ys4[N_ * 8 * B_];    // [n][q][b]: b1 + W1s.x
__device__ __align__(16) float4 g_yt4[N_ * 8 * B_];    // [n][q][b]: W1t.x
__device__ __align__(8)  float2 g_wind2[N_ * B_];      // [n][b]: (speed, dir)
__device__ __align__(16) float4 g_agg4[N_ * 7 * B_];   // [n][g][b]
__device__ __align__(8)  float2 g_agg2[N_ * B_];       // [n][b], outputs 28..29

// 4 sigmoids with ONE reciprocal (5 MUFU instead of 8)
__device__ __forceinline__ void sig4(float& a, float& b, float& c, float& d) {
    float pa = 1.0f + __expf(-a);
    float pb = 1.0f + __expf(-b);
    float pc = 1.0f + __expf(-c);
    float pd = 1.0f + __expf(-d);
    float pab = pa * pb, pcd = pc * pd;
    float r;
    asm("rcp.approx.f32 %0, %1;" : "=f"(r) : "f"(pab * pcd));
    float rab = r * pcd, rcd = r * pab;
    a = rab * pb; b = rab * pa; c = rcd * pd; d = rcd * pc;
}
__device__ __forceinline__ void sig2(float& a, float& b) {
    float pa = 1.0f + __expf(-a);
    float pb = 1.0f + __expf(-b);
    float r;
    asm("rcp.approx.f32 %0, %1;" : "=f"(r) : "f"(pa * pb));
    a = r * pb; b = r * pa;
}

__device__ __forceinline__ ull pack_f2(float lo, float hi) {
    ull r;
    asm("mov.b64 %0, {%1, %2};" : "=l"(r) : "f"(lo), "f"(hi));
    return r;
}
__device__ __forceinline__ void unpack_f2(ull v, float& lo, float& hi) {
    asm("mov.b64 {%0, %1}, %2;" : "=f"(lo), "=f"(hi) : "l"(v));
}
__device__ __forceinline__ ull fma_f2(ull a, ull b, ull c) {
    ull d;
    asm("fma.rn.f32x2 %0, %1, %2, %3;" : "=l"(d) : "l"(a), "l"(b), "l"(c));
    return d;
}
__device__ __forceinline__ ull add_f2(ull a, ull b) {
    ull d;
    asm("add.rn.f32x2 %0, %1, %2;" : "=l"(d) : "l"(a), "l"(b));
    return d;
}
__device__ __forceinline__ void red_v4(float* p, float a, float b, float c, float d) {
    asm volatile("red.global.add.v4.f32 [%0], {%1, %2, %3, %4};"
                 :: "l"(p), "f"(a), "f"(b), "f"(c), "f"(d) : "memory");
}
__device__ __forceinline__ void red_v2(float* p, float a, float b) {
    asm volatile("red.global.add.v2.f32 [%0], {%1, %2};"
                 :: "l"(p), "f"(a), "f"(b) : "memory");
}

// ---- prep: zero agg + pack weights (incl. W2 transpose) + stats + finalize ----
__global__ void __launch_bounds__(256) prep_kernel(
    const float* __restrict__ W1, const float* __restrict__ b1,
    const float* __restrict__ W2, const float* __restrict__ b2,
    const float* __restrict__ Wn, const float* __restrict__ bn,
    const float* __restrict__ wm, const float* __restrict__ ws,
    const float* __restrict__ ea)
{
    // 1) zero aggregates
    float4 z4 = make_float4(0.f, 0.f, 0.f, 0.f);
    for (int i = blockIdx.x * blockDim.x + threadIdx.x; i < N_ * 7 * B_;
         i += gridDim.x * blockDim.x) {
        g_agg4[i] = z4;
    }
    for (int i = blockIdx.x * blockDim.x + threadIdx.x; i < N_ * B_;
         i += gridDim.x * blockDim.x) {
        g_agg2[i] = make_float2(0.f, 0.f);
    }
    // 2) pack weights (block 0)
    if (blockIdx.x == 0) {
        for (int i = threadIdx.x; i < 35 * EH_; i += blockDim.x)
            g_pack.W1[i] = W1[i];
        for (int i = threadIdx.x; i < EH_ * EOUT_; i += blockDim.x) {
            int j = i / EOUT_;
            int o = i % EOUT_;
            g_pack.W2t[o * EH_ + j] = W2[i];
        }
        for (int i = threadIdx.x; i < EOUT_ * NOUT_; i += blockDim.x)
            g_pack.Wn[i] = Wn[i];
        if (threadIdx.x < EH_)   g_pack.b1[threadIdx.x] = b1[threadIdx.x];
        if (threadIdx.x < EOUT_) g_pack.b2[threadIdx.x] = b2[threadIdx.x];
        if (threadIdx.x < NOUT_) g_pack.bn[threadIdx.x] = bn[threadIdx.x];
        if (threadIdx.x < 2) {
            g_pack.wind[threadIdx.x]     = wm[threadIdx.x];
            g_pack.wind[2 + threadIdx.x] = ws[threadIdx.x];
        }
    }
    // 3) stats over edge_attr (double precision)
    double s0 = 0.0, s1 = 0.0, q0 = 0.0, q1 = 0.0;
    for (int i = blockIdx.x * blockDim.x + threadIdx.x; i < E_;
         i += gridDim.x * blockDim.x) {
        float a = ea[2 * i];
        float b = ea[2 * i + 1];
        s0 += (double)a;
        s1 += (double)b;
        q0 += (double)a * (double)a;
        q1 += (double)b * (double)b;
    }
    __shared__ double sh[4][8];
    for (int o = 16; o > 0; o >>= 1) {
        s0 += __shfl_down_sync(0xffffffffu, s0, o);
        s1 += __shfl_down_sync(0xffffffffu, s1, o);
        q0 += __shfl_down_sync(0xffffffffu, q0, o);
        q1 += __shfl_down_sync(0xffffffffu, q1, o);
    }
    int wid = threadIdx.x >> 5;
    if ((threadIdx.x & 31) == 0) {
        sh[0][wid] = s0; sh[1][wid] = s1; sh[2][wid] = q0; sh[3][wid] = q1;
    }
    __syncthreads();
    if (threadIdx.x == 0) {
        double t0 = 0, t1 = 0, t2 = 0, t3 = 0;
        for (int w = 0; w < 8; w++) {
            t0 += sh[0][w]; t1 += sh[1][w]; t2 += sh[2][w]; t3 += sh[3][w];
        }
        g_part[blockIdx.x * 4 + 0] = t0;
        g_part[blockIdx.x * 4 + 1] = t1;
        g_part[blockIdx.x * 4 + 2] = t2;
        g_part[blockIdx.x * 4 + 3] = t3;
    }
    // 4) last-block finalize -> g_pack.norm
    __shared__ bool isLast;
    __threadfence();
    if (threadIdx.x == 0) {
        unsigned old = atomicAdd(&g_counter, 1u);
        isLast = (old == gridDim.x - 1);
    }
    __syncthreads();
    if (isLast) {
        double t[4] = {0, 0, 0, 0};
        for (int i = threadIdx.x; i < (int)gridDim.x; i += blockDim.x) {
            t[0] += g_part[i * 4 + 0];
            t[1] += g_part[i * 4 + 1];
            t[2] += g_part[i * 4 + 2];
            t[3] += g_part[i * 4 + 3];
        }
        for (int c = 0; c < 4; c++) {
            for (int o = 16; o > 0; o >>= 1)
                t[c] += __shfl_down_sync(0xffffffffu, t[c], o);
            if ((threadIdx.x & 31) == 0) sh[c][wid] = t[c];
        }
        __syncthreads();
        if (threadIdx.x == 0) {
            double u0 = 0, u1 = 0, u2 = 0, u3 = 0;
            for (int w = 0; w < 8; w++) {
                u0 += sh[0][w]; u1 += sh[1][w]; u2 += sh[2][w]; u3 += sh[3][w];
            }
            const double n = (double)E_;
            double v0 = (u2 - u0 * u0 / n) / (n - 1.0);
            double v1 = (u3 - u1 * u1 / n) / (n - 1.0);
            g_pack.norm[0] = (float)(u0 / n);
            g_pack.norm[1] = (float)(u1 / n);
            g_pack.norm[2] = (float)(1.0 / sqrt(v0));
            g_pack.norm[3] = (float)(1.0 / sqrt(v1));
            g_counter = 0;   // reset for next graph replay
        }
    }
}

// ---------------- per-node projections: ys = b1 + W1s.x, yt = W1t.x ----------
__global__ void __launch_bounds__(256) proj_kernel(const float* __restrict__ x)
{
    int t = blockIdx.x * blockDim.x + threadIdx.x;   // (n, b)
    if (t >= BN_) return;
    int n = t >> 3;
    int b = t & 7;

    float xv[D_];
    const float4* px = (const float4*)(x + ((size_t)b * N_ + n) * D_);
#pragma unroll
    for (int q = 0; q < 4; q++) {
        float4 v = px[q];
        xv[4 * q + 0] = v.x; xv[4 * q + 1] = v.y;
        xv[4 * q + 2] = v.z; xv[4 * q + 3] = v.w;
    }

    float y[EH_];
#pragma unroll
    for (int j = 0; j < EH_; j++) y[j] = c_p.b1[j];
#pragma unroll
    for (int k = 0; k < D_; k++) {
        float f = xv[k];
#pragma unroll
        for (int j = 0; j < EH_; j++) y[j] = fmaf(f, c_p.W1[k * EH_ + j], y[j]);
    }
    float4* ys = g_ys4 + (size_t)n * (8 * B_) + b;
#pragma unroll
    for (int q = 0; q < 8; q++)
        ys[q * B_] = make_float4(y[4 * q], y[4 * q + 1], y[4 * q + 2], y[4 * q + 3]);

#pragma unroll
    for (int j = 0; j < EH_; j++) y[j] = 0.0f;
#pragma unroll
    for (int k = 0; k < D_; k++) {
        float f = xv[k];
#pragma unroll
        for (int j = 0; j < EH_; j++) y[j] = fmaf(f, c_p.W1[(D_ + k) * EH_ + j], y[j]);
    }
    float4* yt = g_yt4 + (size_t)n * (8 * B_) + b;
#pragma unroll
    for (int q = 0; q < 8; q++)
        yt[q * B_] = make_float4(y[4 * q], y[4 * q + 1], y[4 * q + 2], y[4 * q + 3]);

    g_wind2[(size_t)n * B_ + b] =
        make_float2(fmaf(xv[14], c_p.wind[2], c_p.wind[0]),
                    fmaf(xv[15], c_p.wind[3], c_p.wind[1]));
}

// ---------------- edge kernel: assemble h, layer 2 (const W2t), scatter ----------
__global__ void __launch_bounds__(256) edge_kernel(
    const int* __restrict__ ei, const float* __restrict__ ea)
{
    unsigned gid = blockIdx.x * blockDim.x + threadIdx.x;
    if (gid >= (unsigned)(E_) * B_) return;
    int e = gid >> 3;       // edge id (8 consecutive lanes share it)
    int b = gid & 7;        // batch id
    int src = ei[e];
    int tgt = ei[E_ + e];

    float cd   = ea[2 * e];
    float cdi  = ea[2 * e + 1];
    float ean0 = (cd  - c_p.norm[0]) * c_p.norm[2];
    float ean1 = (cdi - c_p.norm[1]) * c_p.norm[3];

    float2 wd  = g_wind2[(size_t)src * B_ + b];
    float theta = fabsf(cdi - wd.y);
    float ewt   = fmaxf(0.0f, 3.0f * wd.x * __cosf(theta) / cd);

    // ---- layer-1 assembly: h = ys[src] + yt[tgt] + ean0*w32 + ean1*w33 + ewt*w34
    const ulonglong2* ys2 = (const ulonglong2*)(g_ys4 + (size_t)src * (8 * B_) + b);
    const ulonglong2* yt2 = (const ulonglong2*)(g_yt4 + (size_t)tgt * (8 * B_) + b);
    const ulonglong2* w32 = (const ulonglong2*)(c_p.W1 + 32 * EH_);
    const ulonglong2* w33 = (const ulonglong2*)(c_p.W1 + 33 * EH_);
    const ulonglong2* w34 = (const ulonglong2*)(c_p.W1 + 34 * EH_);
    ull e02 = pack_f2(ean0, ean0);
    ull e12 = pack_f2(ean1, ean1);
    ull ew2 = pack_f2(ewt,  ewt);

    ull h2[16];
#pragma unroll
    for (int q = 0; q < 8; q++) {
        ulonglong2 av = ys2[q * B_];
        ulonglong2 cv = yt2[q * B_];
        ulonglong2 v0 = w32[q];
        ulonglong2 v1 = w33[q];
        ulonglong2 v2 = w34[q];
        ull lo = add_f2(av.x, cv.x);
        ull hi = add_f2(av.y, cv.y);
        lo = fma_f2(e02, v0.x, lo);
        hi = fma_f2(e02, v0.y, hi);
        lo = fma_f2(e12, v1.x, lo);
        hi = fma_f2(e12, v1.y, hi);
        lo = fma_f2(ew2, v2.x, lo);
        hi = fma_f2(ew2, v2.y, hi);
        h2[2 * q]     = lo;
        h2[2 * q + 1] = hi;
    }
    // sigmoid (4 at a time, shared reciprocal)
#pragma unroll
    for (int q = 0; q < 8; q++) {
        float a0, a1, a2, a3;
        unpack_f2(h2[2 * q],     a0, a1);
        unpack_f2(h2[2 * q + 1], a2, a3);
        sig4(a0, a1, a2, a3);
        h2[2 * q]     = pack_f2(a0, a1);
        h2[2 * q + 1] = pack_f2(a2, a3);
    }

    // ---- layer 2: weights from CONSTANT (uniform port), coalesced reductions ----
    float4* at4 = g_agg4 + (size_t)tgt * (7 * B_) + b;
    float4* as4 = g_agg4 + (size_t)src * (7 * B_) + b;
#pragma unroll
    for (int g = 0; g < 7; g++) {
        int o0 = 4 * g;
        float ev[4];
#pragma unroll
        for (int t = 0; t < 4; t++) {
            ull acc2 = pack_f2(c_p.b2[o0 + t], 0.0f);
            const ulonglong2* w = (const ulonglong2*)(c_p.W2t + (o0 + t) * EH_);
#pragma unroll
            for (int p = 0; p < 8; p++) {
                ulonglong2 wv = w[p];
                acc2 = fma_f2(h2[2 * p],     wv.x, acc2);
                acc2 = fma_f2(h2[2 * p + 1], wv.y, acc2);
            }
            float lo, hi;
            unpack_f2(acc2, lo, hi);
            ev[t] = lo + hi;
        }
        sig4(ev[0], ev[1], ev[2], ev[3]);
        red_v4((float*)(at4 + g * B_),  ev[0],  ev[1],  ev[2],  ev[3]);
        red_v4((float*)(as4 + g * B_), -ev[0], -ev[1], -ev[2], -ev[3]);
    }
    // outputs 28, 29 -> float2 region
    {
        float ev[2];
#pragma unroll
        for (int t = 0; t < 2; t++) {
            ull acc2 = pack_f2(c_p.b2[28 + t], 0.0f);
            const ulonglong2* w = (const ulonglong2*)(c_p.W2t + (28 + t) * EH_);
#pragma unroll
            for (int p = 0; p < 8; p++) {
                ulonglong2 wv = w[p];
                acc2 = fma_f2(h2[2 * p],     wv.x, acc2);
                acc2 = fma_f2(h2[2 * p + 1], wv.y, acc2);
            }
            float lo, hi;
            unpack_f2(acc2, lo, hi);
            ev[t] = lo + hi;
        }
        sig2(ev[0], ev[1]);
        red_v2((float*)(g_agg2 + (size_t)tgt * B_ + b),  ev[0],  ev[1]);
        red_v2((float*)(g_agg2 + (size_t)src * B_ + b), -ev[0], -ev[1]);
    }
}

// ---------------- node MLP (2 threads per (n,b): 32 outputs each) ------------
__global__ void __launch_bounds__(256) node_kernel(float* __restrict__ out)
{
    int t = blockIdx.x * blockDim.x + threadIdx.x;
    if (t >= BN_ * 2) return;
    int half = t & 1;          // which 32 outputs
    int idx  = t >> 1;         // (n, b)
    int n = idx >> 3;
    int b = idx & 7;
    int obase = half * 32;

    float a[EOUT_];
    const float4* ag = g_agg4 + (size_t)n * (7 * B_) + b;
#pragma unroll
    for (int g = 0; g < 7; g++) {
        float4 v = ag[g * B_];
        a[4 * g + 0] = v.x; a[4 * g + 1] = v.y;
        a[4 * g + 2] = v.z; a[4 * g + 3] = v.w;
    }
    {
        float2 v = g_agg2[(size_t)n * B_ + b];
        a[28] = v.x; a[29] = v.y;
    }

    float* op = out + ((size_t)b * N_ + n) * NOUT_ + obase;
#pragma unroll
    for (int o = 0; o < 32; o += 8) {
        float acc[8];
#pragma unroll
        for (int t2 = 0; t2 < 8; t2++) acc[t2] = c_p.bn[obase + o + t2];
#pragma unroll
        for (int j = 0; j < EOUT_; j++) {
            float aj = a[j];
#pragma unroll
            for (int t2 = 0; t2 < 8; t2++)
                acc[t2] = fmaf(aj, c_p.Wn[j * NOUT_ + obase + o + t2], acc[t2]);
        }
        sig4(acc[0], acc[1], acc[2], acc[3]);
        sig4(acc[4], acc[5], acc[6], acc[7]);
        *(float4*)(op + o)     = make_float4(acc[0], acc[1], acc[2], acc[3]);
        *(float4*)(op + o + 4) = make_float4(acc[4], acc[5], acc[6], acc[7]);
    }
}

// ---------------- launch ----------------
extern "C" void kernel_launch(void* const* d_in, const int* in_sizes, int n_in,
                              void* d_out, int out_size) {
    const float* x  = (const float*)d_in[0];
    const int*   ei = (const int*)d_in[1];
    const float* ea = (const float*)d_in[2];
    const float* wm = (const float*)d_in[3];
    const float* ws = (const float*)d_in[4];
    const float* W1 = (const float*)d_in[5];
    const float* b1 = (const float*)d_in[6];
    const float* W2 = (const float*)d_in[7];
    const float* b2 = (const float*)d_in[8];
    const float* Wn = (const float*)d_in[9];
    const float* bn = (const float*)d_in[10];
    float* out = (float*)d_out;

    // zero agg + pack weights + edge_attr stats + finalize, all in one kernel
    prep_kernel<<<ZGRID_, 256>>>(W1, b1, W2, b2, Wn, bn, wm, ws, ea);

    // single constant-bank staging copy (D2D, capturable)
    void* p = nullptr;
    cudaGetSymbolAddress(&p, g_pack);
    cudaMemcpyToSymbolAsync(c_p, p, sizeof(Pack), 0,
                            cudaMemcpyDeviceToDevice, 0);

    proj_kernel<<<(BN_ + 255) / 256, 256>>>(x);
    edge_kernel<<<(E_ * B_) / 256, 256>>>(ei, ea);
    node_kernel<<<(BN_ * 2 + 255) / 256, 256>>>(out);
}

// round 15
// speedup vs baseline: 1.2031x; 1.2031x over previous
#include <cuda_runtime.h>
#include <math.h>

#define B_     8
#define N_     10000
#define D_     16
#define E_     320000
#define EH_    32
#define EOUT_  30
#define NOUT_  64
#define BN_    (B_ * N_)
#define ZGRID_ 512

typedef unsigned long long ull;

// ---------------- packed constant block (one D2D memcpy) ----------------
struct Pack {
    float W1[35 * EH_];      // layer-1 weights
    float b1[EH_];
    float W2t[EOUT_ * EH_];  // transposed layer-2 [30][32]
    float b2[EOUT_];
    float Wn[EOUT_ * NOUT_];
    float bn[NOUT_];
    float wind[4];           // wm0, wm1, ws0, ws1
    float norm[4];           // mean0, mean1, rstd0, rstd1
};
__constant__ Pack c_p;
__device__ Pack g_pack;     // staged by prep_kernel

// ---------------- device scratch ----------------
__device__ double g_part[ZGRID_ * 4];
__device__ unsigned g_counter = 0;
__device__ __align__(16) float4 g_ys4[N_ * 8 * B_];    // [n][q][b]: b1 + W1s.x
__device__ __align__(16) float4 g_yt4[N_ * 8 * B_];    // [n][q][b]: W1t.x
__device__ __align__(8)  float2 g_wind2[N_ * B_];      // [n][b]: (speed, dir)
__device__ __align__(16) float4 g_agg4[N_ * 7 * B_];   // [n][g][b]
__device__ __align__(8)  float2 g_agg2[N_ * B_];       // [n][b], outputs 28..29

// 4 sigmoids with ONE reciprocal (5 MUFU instead of 8)
__device__ __forceinline__ void sig4(float& a, float& b, float& c, float& d) {
    float pa = 1.0f + __expf(-a);
    float pb = 1.0f + __expf(-b);
    float pc = 1.0f + __expf(-c);
    float pd = 1.0f + __expf(-d);
    float pab = pa * pb, pcd = pc * pd;
    float r;
    asm("rcp.approx.f32 %0, %1;" : "=f"(r) : "f"(pab * pcd));
    float rab = r * pcd, rcd = r * pab;
    a = rab * pb; b = rab * pa; c = rcd * pd; d = rcd * pc;
}
__device__ __forceinline__ void sig2(float& a, float& b) {
    float pa = 1.0f + __expf(-a);
    float pb = 1.0f + __expf(-b);
    float r;
    asm("rcp.approx.f32 %0, %1;" : "=f"(r) : "f"(pa * pb));
    a = r * pb; b = r * pa;
}

__device__ __forceinline__ ull pack_f2(float lo, float hi) {
    ull r;
    asm("mov.b64 %0, {%1, %2};" : "=l"(r) : "f"(lo), "f"(hi));
    return r;
}
__device__ __forceinline__ void unpack_f2(ull v, float& lo, float& hi) {
    asm("mov.b64 {%0, %1}, %2;" : "=f"(lo), "=f"(hi) : "l"(v));
}
__device__ __forceinline__ ull fma_f2(ull a, ull b, ull c) {
    ull d;
    asm("fma.rn.f32x2 %0, %1, %2, %3;" : "=l"(d) : "l"(a), "l"(b), "l"(c));
    return d;
}
__device__ __forceinline__ ull add_f2(ull a, ull b) {
    ull d;
    asm("add.rn.f32x2 %0, %1, %2;" : "=l"(d) : "l"(a), "l"(b));
    return d;
}
__device__ __forceinline__ void red_v4(float* p, float a, float b, float c, float d) {
    asm volatile("red.global.add.v4.f32 [%0], {%1, %2, %3, %4};"
                 :: "l"(p), "f"(a), "f"(b), "f"(c), "f"(d) : "memory");
}
__device__ __forceinline__ void red_v2(float* p, float a, float b) {
    asm volatile("red.global.add.v2.f32 [%0], {%1, %2};"
                 :: "l"(p), "f"(a), "f"(b) : "memory");
}

// ---- prep: zero agg + pack weights (incl. W2 transpose) + stats + finalize ----
__global__ void __launch_bounds__(256) prep_kernel(
    const float* __restrict__ W1, const float* __restrict__ b1,
    const float* __restrict__ W2, const float* __restrict__ b2,
    const float* __restrict__ Wn, const float* __restrict__ bn,
    const float* __restrict__ wm, const float* __restrict__ ws,
    const float* __restrict__ ea)
{
    // 1) zero aggregates
    float4 z4 = make_float4(0.f, 0.f, 0.f, 0.f);
    for (int i = blockIdx.x * blockDim.x + threadIdx.x; i < N_ * 7 * B_;
         i += gridDim.x * blockDim.x) {
        g_agg4[i] = z4;
    }
    for (int i = blockIdx.x * blockDim.x + threadIdx.x; i < N_ * B_;
         i += gridDim.x * blockDim.x) {
        g_agg2[i] = make_float2(0.f, 0.f);
    }
    // 2) pack weights (block 0)
    if (blockIdx.x == 0) {
        for (int i = threadIdx.x; i < 35 * EH_; i += blockDim.x)
            g_pack.W1[i] = W1[i];
        for (int i = threadIdx.x; i < EH_ * EOUT_; i += blockDim.x) {
            int j = i / EOUT_;
            int o = i % EOUT_;
            g_pack.W2t[o * EH_ + j] = W2[i];
        }
        for (int i = threadIdx.x; i < EOUT_ * NOUT_; i += blockDim.x)
            g_pack.Wn[i] = Wn[i];
        if (threadIdx.x < EH_)   g_pack.b1[threadIdx.x] = b1[threadIdx.x];
        if (threadIdx.x < EOUT_) g_pack.b2[threadIdx.x] = b2[threadIdx.x];
        if (threadIdx.x < NOUT_) g_pack.bn[threadIdx.x] = bn[threadIdx.x];
        if (threadIdx.x < 2) {
            g_pack.wind[threadIdx.x]     = wm[threadIdx.x];
            g_pack.wind[2 + threadIdx.x] = ws[threadIdx.x];
        }
    }
    // 3) stats over edge_attr (double precision)
    double s0 = 0.0, s1 = 0.0, q0 = 0.0, q1 = 0.0;
    for (int i = blockIdx.x * blockDim.x + threadIdx.x; i < E_;
         i += gridDim.x * blockDim.x) {
        float a = ea[2 * i];
        float b = ea[2 * i + 1];
        s0 += (double)a;
        s1 += (double)b;
        q0 += (double)a * (double)a;
        q1 += (double)b * (double)b;
    }
    __shared__ double sh[4][8];
    for (int o = 16; o > 0; o >>= 1) {
        s0 += __shfl_down_sync(0xffffffffu, s0, o);
        s1 += __shfl_down_sync(0xffffffffu, s1, o);
        q0 += __shfl_down_sync(0xffffffffu, q0, o);
        q1 += __shfl_down_sync(0xffffffffu, q1, o);
    }
    int wid = threadIdx.x >> 5;
    if ((threadIdx.x & 31) == 0) {
        sh[0][wid] = s0; sh[1][wid] = s1; sh[2][wid] = q0; sh[3][wid] = q1;
    }
    __syncthreads();
    if (threadIdx.x == 0) {
        double t0 = 0, t1 = 0, t2 = 0, t3 = 0;
        for (int w = 0; w < 8; w++) {
            t0 += sh[0][w]; t1 += sh[1][w]; t2 += sh[2][w]; t3 += sh[3][w];
        }
        g_part[blockIdx.x * 4 + 0] = t0;
        g_part[blockIdx.x * 4 + 1] = t1;
        g_part[blockIdx.x * 4 + 2] = t2;
        g_part[blockIdx.x * 4 + 3] = t3;
    }
    // 4) last-block finalize -> g_pack.norm
    __shared__ bool isLast;
    __threadfence();
    if (threadIdx.x == 0) {
        unsigned old = atomicAdd(&g_counter, 1u);
        isLast = (old == gridDim.x - 1);
    }
    __syncthreads();
    if (isLast) {
        double t[4] = {0, 0, 0, 0};
        for (int i = threadIdx.x; i < (int)gridDim.x; i += blockDim.x) {
            t[0] += g_part[i * 4 + 0];
            t[1] += g_part[i * 4 + 1];
            t[2] += g_part[i * 4 + 2];
            t[3] += g_part[i * 4 + 3];
        }
        for (int c = 0; c < 4; c++) {
            for (int o = 16; o > 0; o >>= 1)
                t[c] += __shfl_down_sync(0xffffffffu, t[c], o);
            if ((threadIdx.x & 31) == 0) sh[c][wid] = t[c];
        }
        __syncthreads();
        if (threadIdx.x == 0) {
            double u0 = 0, u1 = 0, u2 = 0, u3 = 0;
            for (int w = 0; w < 8; w++) {
                u0 += sh[0][w]; u1 += sh[1][w]; u2 += sh[2][w]; u3 += sh[3][w];
            }
            const double n = (double)E_;
            double v0 = (u2 - u0 * u0 / n) / (n - 1.0);
            double v1 = (u3 - u1 * u1 / n) / (n - 1.0);
            g_pack.norm[0] = (float)(u0 / n);
            g_pack.norm[1] = (float)(u1 / n);
            g_pack.norm[2] = (float)(1.0 / sqrt(v0));
            g_pack.norm[3] = (float)(1.0 / sqrt(v1));
            g_counter = 0;   // reset for next graph replay
        }
    }
}

// ---------------- per-node projections: ys = b1 + W1s.x, yt = W1t.x ----------
__global__ void __launch_bounds__(256) proj_kernel(const float* __restrict__ x)
{
    int t = blockIdx.x * blockDim.x + threadIdx.x;   // (n, b)
    if (t >= BN_) return;
    int n = t >> 3;
    int b = t & 7;

    float xv[D_];
    const float4* px = (const float4*)(x + ((size_t)b * N_ + n) * D_);
#pragma unroll
    for (int q = 0; q < 4; q++) {
        float4 v = px[q];
        xv[4 * q + 0] = v.x; xv[4 * q + 1] = v.y;
        xv[4 * q + 2] = v.z; xv[4 * q + 3] = v.w;
    }

    float y[EH_];
#pragma unroll
    for (int j = 0; j < EH_; j++) y[j] = c_p.b1[j];
#pragma unroll
    for (int k = 0; k < D_; k++) {
        float f = xv[k];
#pragma unroll
        for (int j = 0; j < EH_; j++) y[j] = fmaf(f, c_p.W1[k * EH_ + j], y[j]);
    }
    float4* ys = g_ys4 + (size_t)n * (8 * B_) + b;
#pragma unroll
    for (int q = 0; q < 8; q++)
        ys[q * B_] = make_float4(y[4 * q], y[4 * q + 1], y[4 * q + 2], y[4 * q + 3]);

#pragma unroll
    for (int j = 0; j < EH_; j++) y[j] = 0.0f;
#pragma unroll
    for (int k = 0; k < D_; k++) {
        float f = xv[k];
#pragma unroll
        for (int j = 0; j < EH_; j++) y[j] = fmaf(f, c_p.W1[(D_ + k) * EH_ + j], y[j]);
    }
    float4* yt = g_yt4 + (size_t)n * (8 * B_) + b;
#pragma unroll
    for (int q = 0; q < 8; q++)
        yt[q * B_] = make_float4(y[4 * q], y[4 * q + 1], y[4 * q + 2], y[4 * q + 3]);

    g_wind2[(size_t)n * B_ + b] =
        make_float2(fmaf(xv[14], c_p.wind[2], c_p.wind[0]),
                    fmaf(xv[15], c_p.wind[3], c_p.wind[1]));
}

// ---------------- edge kernel: assemble h, layer 2 (const W2t), scatter ----------
__global__ void __launch_bounds__(256) edge_kernel(
    const int* __restrict__ ei, const float* __restrict__ ea)
{
    unsigned gid = blockIdx.x * blockDim.x + threadIdx.x;
    if (gid >= (unsigned)(E_) * B_) return;
    int e = gid >> 3;       // edge id (8 consecutive lanes share it)
    int b = gid & 7;        // batch id
    int src = ei[e];
    int tgt = ei[E_ + e];

    float cd   = ea[2 * e];
    float cdi  = ea[2 * e + 1];
    float ean0 = (cd  - c_p.norm[0]) * c_p.norm[2];
    float ean1 = (cdi - c_p.norm[1]) * c_p.norm[3];

    float2 wd  = g_wind2[(size_t)src * B_ + b];
    float theta = fabsf(cdi - wd.y);
    float ewt   = fmaxf(0.0f, 3.0f * wd.x * __cosf(theta) / cd);

    // ---- layer-1 assembly: h = ys[src] + yt[tgt] + ean0*w32 + ean1*w33 + ewt*w34
    const ulonglong2* ys2 = (const ulonglong2*)(g_ys4 + (size_t)src * (8 * B_) + b);
    const ulonglong2* yt2 = (const ulonglong2*)(g_yt4 + (size_t)tgt * (8 * B_) + b);
    const ulonglong2* w32 = (const ulonglong2*)(c_p.W1 + 32 * EH_);
    const ulonglong2* w33 = (const ulonglong2*)(c_p.W1 + 33 * EH_);
    const ulonglong2* w34 = (const ulonglong2*)(c_p.W1 + 34 * EH_);
    ull e02 = pack_f2(ean0, ean0);
    ull e12 = pack_f2(ean1, ean1);
    ull ew2 = pack_f2(ewt,  ewt);

    ull h2[16];
#pragma unroll
    for (int q = 0; q < 8; q++) {
        ulonglong2 av = ys2[q * B_];
        ulonglong2 cv = yt2[q * B_];
        ulonglong2 v0 = w32[q];
        ulonglong2 v1 = w33[q];
        ulonglong2 v2 = w34[q];
        ull lo = add_f2(av.x, cv.x);
        ull hi = add_f2(av.y, cv.y);
        lo = fma_f2(e02, v0.x, lo);
        hi = fma_f2(e02, v0.y, hi);
        lo = fma_f2(e12, v1.x, lo);
        hi = fma_f2(e12, v1.y, hi);
        lo = fma_f2(ew2, v2.x, lo);
        hi = fma_f2(ew2, v2.y, hi);
        h2[2 * q]     = lo;
        h2[2 * q + 1] = hi;
    }
    // sigmoid (4 at a time, shared reciprocal)
#pragma unroll
    for (int q = 0; q < 8; q++) {
        float a0, a1, a2, a3;
        unpack_f2(h2[2 * q],     a0, a1);
        unpack_f2(h2[2 * q + 1], a2, a3);
        sig4(a0, a1, a2, a3);
        h2[2 * q]     = pack_f2(a0, a1);
        h2[2 * q + 1] = pack_f2(a2, a3);
    }

    // ---- layer 2: weights from CONSTANT (uniform port), coalesced reductions ----
    float4* at4 = g_agg4 + (size_t)tgt * (7 * B_) + b;
    float4* as4 = g_agg4 + (size_t)src * (7 * B_) + b;
#pragma unroll
    for (int g = 0; g < 7; g++) {
        int o0 = 4 * g;
        float ev[4];
#pragma unroll
        for (int t = 0; t < 4; t++) {
            ull acc2 = pack_f2(c_p.b2[o0 + t], 0.0f);
            const ulonglong2* w = (const ulonglong2*)(c_p.W2t + (o0 + t) * EH_);
#pragma unroll
            for (int p = 0; p < 8; p++) {
                ulonglong2 wv = w[p];
                acc2 = fma_f2(h2[2 * p],     wv.x, acc2);
                acc2 = fma_f2(h2[2 * p + 1], wv.y, acc2);
            }
            float lo, hi;
            unpack_f2(acc2, lo, hi);
            ev[t] = lo + hi;
        }
        sig4(ev[0], ev[1], ev[2], ev[3]);
        red_v4((float*)(at4 + g * B_),  ev[0],  ev[1],  ev[2],  ev[3]);
        red_v4((float*)(as4 + g * B_), -ev[0], -ev[1], -ev[2], -ev[3]);
    }
    // outputs 28, 29 -> float2 region
    {
        float ev[2];
#pragma unroll
        for (int t = 0; t < 2; t++) {
            ull acc2 = pack_f2(c_p.b2[28 + t], 0.0f);
            const ulonglong2* w = (const ulonglong2*)(c_p.W2t + (28 + t) * EH_);
#pragma unroll
            for (int p = 0; p < 8; p++) {
                ulonglong2 wv = w[p];
                acc2 = fma_f2(h2[2 * p],     wv.x, acc2);
                acc2 = fma_f2(h2[2 * p + 1], wv.y, acc2);
            }
            float lo, hi;
            unpack_f2(acc2, lo, hi);
            ev[t] = lo + hi;
        }
        sig2(ev[0], ev[1]);
        red_v2((float*)(g_agg2 + (size_t)tgt * B_ + b),  ev[0],  ev[1]);
        red_v2((float*)(g_agg2 + (size_t)src * B_ + b), -ev[0], -ev[1]);
    }
}

// ---- node MLP (2 threads per (n,b), WARP-UNIFORM half: t < BN_ -> lo 32) ----
__global__ void __launch_bounds__(256) node_kernel(float* __restrict__ out)
{
    int t = blockIdx.x * blockDim.x + threadIdx.x;
    if (t >= BN_ * 2) return;
    int half = (t >= BN_) ? 1 : 0;   // warp-uniform (BN_ = 80000 = 312.5 warps... 
                                     // 80000 % 32 == 0, so no warp straddles)
    int idx  = t - half * BN_;       // (n, b)
    int n = idx >> 3;
    int b = idx & 7;
    int obase = half * 32;

    float a[EOUT_];
    const float4* ag = g_agg4 + (size_t)n * (7 * B_) + b;
#pragma unroll
    for (int g = 0; g < 7; g++) {
        float4 v = ag[g * B_];
        a[4 * g + 0] = v.x; a[4 * g + 1] = v.y;
        a[4 * g + 2] = v.z; a[4 * g + 3] = v.w;
    }
    {
        float2 v = g_agg2[(size_t)n * B_ + b];
        a[28] = v.x; a[29] = v.y;
    }

    float* op = out + ((size_t)b * N_ + n) * NOUT_ + obase;
#pragma unroll
    for (int o = 0; o < 32; o += 8) {
        float acc[8];
#pragma unroll
        for (int t2 = 0; t2 < 8; t2++) acc[t2] = c_p.bn[obase + o + t2];
#pragma unroll
        for (int j = 0; j < EOUT_; j++) {
            float aj = a[j];
#pragma unroll
            for (int t2 = 0; t2 < 8; t2++)
                acc[t2] = fmaf(aj, c_p.Wn[j * NOUT_ + obase + o + t2], acc[t2]);
        }
        sig4(acc[0], acc[1], acc[2], acc[3]);
        sig4(acc[4], acc[5], acc[6], acc[7]);
        *(float4*)(op + o)     = make_float4(acc[0], acc[1], acc[2], acc[3]);
        *(float4*)(op + o + 4) = make_float4(acc[4], acc[5], acc[6], acc[7]);
    }
}

// ---------------- launch ----------------
extern "C" void kernel_launch(void* const* d_in, const int* in_sizes, int n_in,
                              void* d_out, int out_size) {
    const float* x  = (const float*)d_in[0];
    const int*   ei = (const int*)d_in[1];
    const float* ea = (const float*)d_in[2];
    const float* wm = (const float*)d_in[3];
    const float* ws = (const float*)d_in[4];
    const float* W1 = (const float*)d_in[5];
    const float* b1 = (const float*)d_in[6];
    const float* W2 = (const float*)d_in[7];
    const float* b2 = (const float*)d_in[8];
    const float* Wn = (const float*)d_in[9];
    const float* bn = (const float*)d_in[10];
    float* out = (float*)d_out;

    // zero agg + pack weights + edge_attr stats + finalize, all in one kernel
    prep_kernel<<<ZGRID_, 256>>>(W1, b1, W2, b2, Wn, bn, wm, ws, ea);

    // single constant-bank staging copy (D2D, capturable)
    void* p = nullptr;
    cudaGetSymbolAddress(&p, g_pack);
    cudaMemcpyToSymbolAsync(c_p, p, sizeof(Pack), 0,
                            cudaMemcpyDeviceToDevice, 0);

    proj_kernel<<<(BN_ + 255) / 256, 256>>>(x);
    edge_kernel<<<(E_ * B_) / 256, 256>>>(ei, ea);
    node_kernel<<<(BN_ * 2 + 255) / 256, 256>>>(out);
}

// round 16
// speedup vs baseline: 1.5370x; 1.2775x over previous
#include <cuda_runtime.h>
#include <math.h>

#define B_     8
#define N_     10000
#define D_     16
#define E_     320000
#define EH_    32
#define EOUT_  30
#define NOUT_  64
#define BN_    (B_ * N_)
#define ZGRID_ 512

typedef unsigned long long ull;

// ---------------- packed constant block (one D2D memcpy) ----------------
struct Pack {
    float W1[35 * EH_];      // layer-1 weights
    float b1[EH_];
    float W2t[EOUT_ * EH_];  // transposed layer-2 [30][32]
    float b2[EOUT_];
    float Wn[EOUT_ * NOUT_];
    float bn[NOUT_];
    float wind[4];           // wm0, wm1, ws0, ws1
    float norm[4];           // mean0, mean1, rstd0, rstd1
};
__constant__ Pack c_p;
__device__ Pack g_pack;     // staged by prep_kernel

// ---------------- device scratch ----------------
__device__ double g_part[ZGRID_ * 4];
__device__ unsigned g_counter = 0;
__device__ __align__(16) float4 g_ys4[N_ * 8 * B_];    // [n][q][b]: b1 + W1s.x
__device__ __align__(16) float4 g_yt4[N_ * 8 * B_];    // [n][q][b]: W1t.x
__device__ __align__(8)  float2 g_wind2[N_ * B_];      // [n][b]: (speed, dir)
__device__ __align__(16) float4 g_agg4[N_ * 7 * B_];   // [n][g][b]
__device__ __align__(8)  float2 g_agg2[N_ * B_];       // [n][b], outputs 28..29

// 4 sigmoids with ONE reciprocal (5 MUFU instead of 8)
__device__ __forceinline__ void sig4(float& a, float& b, float& c, float& d) {
    float pa = 1.0f + __expf(-a);
    float pb = 1.0f + __expf(-b);
    float pc = 1.0f + __expf(-c);
    float pd = 1.0f + __expf(-d);
    float pab = pa * pb, pcd = pc * pd;
    float r;
    asm("rcp.approx.f32 %0, %1;" : "=f"(r) : "f"(pab * pcd));
    float rab = r * pcd, rcd = r * pab;
    a = rab * pb; b = rab * pa; c = rcd * pd; d = rcd * pc;
}
__device__ __forceinline__ void sig2(float& a, float& b) {
    float pa = 1.0f + __expf(-a);
    float pb = 1.0f + __expf(-b);
    float r;
    asm("rcp.approx.f32 %0, %1;" : "=f"(r) : "f"(pa * pb));
    a = r * pb; b = r * pa;
}

__device__ __forceinline__ ull pack_f2(float lo, float hi) {
    ull r;
    asm("mov.b64 %0, {%1, %2};" : "=l"(r) : "f"(lo), "f"(hi));
    return r;
}
__device__ __forceinline__ void unpack_f2(ull v, float& lo, float& hi) {
    asm("mov.b64 {%0, %1}, %2;" : "=f"(lo), "=f"(hi) : "l"(v));
}
__device__ __forceinline__ ull fma_f2(ull a, ull b, ull c) {
    ull d;
    asm("fma.rn.f32x2 %0, %1, %2, %3;" : "=l"(d) : "l"(a), "l"(b), "l"(c));
    return d;
}
__device__ __forceinline__ ull add_f2(ull a, ull b) {
    ull d;
    asm("add.rn.f32x2 %0, %1, %2;" : "=l"(d) : "l"(a), "l"(b));
    return d;
}
__device__ __forceinline__ void red_v4(float* p, float a, float b, float c, float d) {
    asm volatile("red.global.add.v4.f32 [%0], {%1, %2, %3, %4};"
                 :: "l"(p), "f"(a), "f"(b), "f"(c), "f"(d) : "memory");
}
__device__ __forceinline__ void red_v2(float* p, float a, float b) {
    asm volatile("red.global.add.v2.f32 [%0], {%1, %2};"
                 :: "l"(p), "f"(a), "f"(b) : "memory");
}

// ---- prep: zero agg + pack weights (incl. W2 transpose) + stats + finalize ----
__global__ void __launch_bounds__(256) prep_kernel(
    const float* __restrict__ W1, const float* __restrict__ b1,
    const float* __restrict__ W2, const float* __restrict__ b2,
    const float* __restrict__ Wn, const float* __restrict__ bn,
    const float* __restrict__ wm, const float* __restrict__ ws,
    const float* __restrict__ ea)
{
    // 1) zero aggregates
    float4 z4 = make_float4(0.f, 0.f, 0.f, 0.f);
    for (int i = blockIdx.x * blockDim.x + threadIdx.x; i < N_ * 7 * B_;
         i += gridDim.x * blockDim.x) {
        g_agg4[i] = z4;
    }
    for (int i = blockIdx.x * blockDim.x + threadIdx.x; i < N_ * B_;
         i += gridDim.x * blockDim.x) {
        g_agg2[i] = make_float2(0.f, 0.f);
    }
    // 2) pack weights (block 0)
    if (blockIdx.x == 0) {
        for (int i = threadIdx.x; i < 35 * EH_; i += blockDim.x)
            g_pack.W1[i] = W1[i];
        for (int i = threadIdx.x; i < EH_ * EOUT_; i += blockDim.x) {
            int j = i / EOUT_;
            int o = i % EOUT_;
            g_pack.W2t[o * EH_ + j] = W2[i];
        }
        for (int i = threadIdx.x; i < EOUT_ * NOUT_; i += blockDim.x)
            g_pack.Wn[i] = Wn[i];
        if (threadIdx.x < EH_)   g_pack.b1[threadIdx.x] = b1[threadIdx.x];
        if (threadIdx.x < EOUT_) g_pack.b2[threadIdx.x] = b2[threadIdx.x];
        if (threadIdx.x < NOUT_) g_pack.bn[threadIdx.x] = bn[threadIdx.x];
        if (threadIdx.x < 2) {
            g_pack.wind[threadIdx.x]     = wm[threadIdx.x];
            g_pack.wind[2 + threadIdx.x] = ws[threadIdx.x];
        }
    }
    // 3) stats over edge_attr (double precision)
    double s0 = 0.0, s1 = 0.0, q0 = 0.0, q1 = 0.0;
    for (int i = blockIdx.x * blockDim.x + threadIdx.x; i < E_;
         i += gridDim.x * blockDim.x) {
        float a = ea[2 * i];
        float b = ea[2 * i + 1];
        s0 += (double)a;
        s1 += (double)b;
        q0 += (double)a * (double)a;
        q1 += (double)b * (double)b;
    }
    __shared__ double sh[4][8];
    for (int o = 16; o > 0; o >>= 1) {
        s0 += __shfl_down_sync(0xffffffffu, s0, o);
        s1 += __shfl_down_sync(0xffffffffu, s1, o);
        q0 += __shfl_down_sync(0xffffffffu, q0, o);
        q1 += __shfl_down_sync(0xffffffffu, q1, o);
    }
    int wid = threadIdx.x >> 5;
    if ((threadIdx.x & 31) == 0) {
        sh[0][wid] = s0; sh[1][wid] = s1; sh[2][wid] = q0; sh[3][wid] = q1;
    }
    __syncthreads();
    if (threadIdx.x == 0) {
        double t0 = 0, t1 = 0, t2 = 0, t3 = 0;
        for (int w = 0; w < 8; w++) {
            t0 += sh[0][w]; t1 += sh[1][w]; t2 += sh[2][w]; t3 += sh[3][w];
        }
        g_part[blockIdx.x * 4 + 0] = t0;
        g_part[blockIdx.x * 4 + 1] = t1;
        g_part[blockIdx.x * 4 + 2] = t2;
        g_part[blockIdx.x * 4 + 3] = t3;
    }
    // 4) last-block finalize -> g_pack.norm
    __shared__ bool isLast;
    __threadfence();
    if (threadIdx.x == 0) {
        unsigned old = atomicAdd(&g_counter, 1u);
        isLast = (old == gridDim.x - 1);
    }
    __syncthreads();
    if (isLast) {
        double t[4] = {0, 0, 0, 0};
        for (int i = threadIdx.x; i < (int)gridDim.x; i += blockDim.x) {
            t[0] += g_part[i * 4 + 0];
            t[1] += g_part[i * 4 + 1];
            t[2] += g_part[i * 4 + 2];
            t[3] += g_part[i * 4 + 3];
        }
        for (int c = 0; c < 4; c++) {
            for (int o = 16; o > 0; o >>= 1)
                t[c] += __shfl_down_sync(0xffffffffu, t[c], o);
            if ((threadIdx.x & 31) == 0) sh[c][wid] = t[c];
        }
        __syncthreads();
        if (threadIdx.x == 0) {
            double u0 = 0, u1 = 0, u2 = 0, u3 = 0;
            for (int w = 0; w < 8; w++) {
                u0 += sh[0][w]; u1 += sh[1][w]; u2 += sh[2][w]; u3 += sh[3][w];
            }
            const double n = (double)E_;
            double v0 = (u2 - u0 * u0 / n) / (n - 1.0);
            double v1 = (u3 - u1 * u1 / n) / (n - 1.0);
            g_pack.norm[0] = (float)(u0 / n);
            g_pack.norm[1] = (float)(u1 / n);
            g_pack.norm[2] = (float)(1.0 / sqrt(v0));
            g_pack.norm[3] = (float)(1.0 / sqrt(v1));
            g_counter = 0;   // reset for next graph replay
        }
    }
}

// ---------------- per-node projections: ys = b1 + W1s.x, yt = W1t.x ----------
__global__ void __launch_bounds__(256) proj_kernel(const float* __restrict__ x)
{
    int t = blockIdx.x * blockDim.x + threadIdx.x;   // (n, b)
    if (t >= BN_) return;
    int n = t >> 3;
    int b = t & 7;

    float xv[D_];
    const float4* px = (const float4*)(x + ((size_t)b * N_ + n) * D_);
#pragma unroll
    for (int q = 0; q < 4; q++) {
        float4 v = px[q];
        xv[4 * q + 0] = v.x; xv[4 * q + 1] = v.y;
        xv[4 * q + 2] = v.z; xv[4 * q + 3] = v.w;
    }

    float y[EH_];
#pragma unroll
    for (int j = 0; j < EH_; j++) y[j] = c_p.b1[j];
#pragma unroll
    for (int k = 0; k < D_; k++) {
        float f = xv[k];
#pragma unroll
        for (int j = 0; j < EH_; j++) y[j] = fmaf(f, c_p.W1[k * EH_ + j], y[j]);
    }
    float4* ys = g_ys4 + (size_t)n * (8 * B_) + b;
#pragma unroll
    for (int q = 0; q < 8; q++)
        ys[q * B_] = make_float4(y[4 * q], y[4 * q + 1], y[4 * q + 2], y[4 * q + 3]);

#pragma unroll
    for (int j = 0; j < EH_; j++) y[j] = 0.0f;
#pragma unroll
    for (int k = 0; k < D_; k++) {
        float f = xv[k];
#pragma unroll
        for (int j = 0; j < EH_; j++) y[j] = fmaf(f, c_p.W1[(D_ + k) * EH_ + j], y[j]);
    }
    float4* yt = g_yt4 + (size_t)n * (8 * B_) + b;
#pragma unroll
    for (int q = 0; q < 8; q++)
        yt[q * B_] = make_float4(y[4 * q], y[4 * q + 1], y[4 * q + 2], y[4 * q + 3]);

    g_wind2[(size_t)n * B_ + b] =
        make_float2(fmaf(xv[14], c_p.wind[2], c_p.wind[0]),
                    fmaf(xv[15], c_p.wind[3], c_p.wind[1]));
}

// ---------------- edge kernel: assemble h, layer 2 (const W2t), scatter ----------
__global__ void __launch_bounds__(256) edge_kernel(
    const int* __restrict__ ei, const float* __restrict__ ea)
{
    unsigned gid = blockIdx.x * blockDim.x + threadIdx.x;
    if (gid >= (unsigned)(E_) * B_) return;
    int e = gid >> 3;       // edge id (8 consecutive lanes share it)
    int b = gid & 7;        // batch id
    int src = ei[e];
    int tgt = ei[E_ + e];

    float cd   = ea[2 * e];
    float cdi  = ea[2 * e + 1];
    float ean0 = (cd  - c_p.norm[0]) * c_p.norm[2];
    float ean1 = (cdi - c_p.norm[1]) * c_p.norm[3];

    float2 wd  = g_wind2[(size_t)src * B_ + b];
    float theta = fabsf(cdi - wd.y);
    float ewt   = fmaxf(0.0f, 3.0f * wd.x * __cosf(theta) / cd);

    // ---- layer-1 assembly: h = ys[src] + yt[tgt] + ean0*w32 + ean1*w33 + ewt*w34
    const ulonglong2* ys2 = (const ulonglong2*)(g_ys4 + (size_t)src * (8 * B_) + b);
    const ulonglong2* yt2 = (const ulonglong2*)(g_yt4 + (size_t)tgt * (8 * B_) + b);
    const ulonglong2* w32 = (const ulonglong2*)(c_p.W1 + 32 * EH_);
    const ulonglong2* w33 = (const ulonglong2*)(c_p.W1 + 33 * EH_);
    const ulonglong2* w34 = (const ulonglong2*)(c_p.W1 + 34 * EH_);
    ull e02 = pack_f2(ean0, ean0);
    ull e12 = pack_f2(ean1, ean1);
    ull ew2 = pack_f2(ewt,  ewt);

    ull h2[16];
#pragma unroll
    for (int q = 0; q < 8; q++) {
        ulonglong2 av = ys2[q * B_];
        ulonglong2 cv = yt2[q * B_];
        ulonglong2 v0 = w32[q];
        ulonglong2 v1 = w33[q];
        ulonglong2 v2 = w34[q];
        ull lo = add_f2(av.x, cv.x);
        ull hi = add_f2(av.y, cv.y);
        lo = fma_f2(e02, v0.x, lo);
        hi = fma_f2(e02, v0.y, hi);
        lo = fma_f2(e12, v1.x, lo);
        hi = fma_f2(e12, v1.y, hi);
        lo = fma_f2(ew2, v2.x, lo);
        hi = fma_f2(ew2, v2.y, hi);
        h2[2 * q]     = lo;
        h2[2 * q + 1] = hi;
    }
    // sigmoid (4 at a time, shared reciprocal)
#pragma unroll
    for (int q = 0; q < 8; q++) {
        float a0, a1, a2, a3;
        unpack_f2(h2[2 * q],     a0, a1);
        unpack_f2(h2[2 * q + 1], a2, a3);
        sig4(a0, a1, a2, a3);
        h2[2 * q]     = pack_f2(a0, a1);
        h2[2 * q + 1] = pack_f2(a2, a3);
    }

    // ---- layer 2: weights from CONSTANT (uniform port), coalesced reductions ----
    float4* at4 = g_agg4 + (size_t)tgt * (7 * B_) + b;
    float4* as4 = g_agg4 + (size_t)src * (7 * B_) + b;
#pragma unroll
    for (int g = 0; g < 7; g++) {
        int o0 = 4 * g;
        float ev[4];
#pragma unroll
        for (int t = 0; t < 4; t++) {
            ull acc2 = pack_f2(c_p.b2[o0 + t], 0.0f);
            const ulonglong2* w = (const ulonglong2*)(c_p.W2t + (o0 + t) * EH_);
#pragma unroll
            for (int p = 0; p < 8; p++) {
                ulonglong2 wv = w[p];
                acc2 = fma_f2(h2[2 * p],     wv.x, acc2);
                acc2 = fma_f2(h2[2 * p + 1], wv.y, acc2);
            }
            float lo, hi;
            unpack_f2(acc2, lo, hi);
            ev[t] = lo + hi;
        }
        sig4(ev[0], ev[1], ev[2], ev[3]);
        red_v4((float*)(at4 + g * B_),  ev[0],  ev[1],  ev[2],  ev[3]);
        red_v4((float*)(as4 + g * B_), -ev[0], -ev[1], -ev[2], -ev[3]);
    }
    // outputs 28, 29 -> float2 region
    {
        float ev[2];
#pragma unroll
        for (int t = 0; t < 2; t++) {
            ull acc2 = pack_f2(c_p.b2[28 + t], 0.0f);
            const ulonglong2* w = (const ulonglong2*)(c_p.W2t + (28 + t) * EH_);
#pragma unroll
            for (int p = 0; p < 8; p++) {
                ulonglong2 wv = w[p];
                acc2 = fma_f2(h2[2 * p],     wv.x, acc2);
                acc2 = fma_f2(h2[2 * p + 1], wv.y, acc2);
            }
            float lo, hi;
            unpack_f2(acc2, lo, hi);
            ev[t] = lo + hi;
        }
        sig2(ev[0], ev[1]);
        red_v2((float*)(g_agg2 + (size_t)tgt * B_ + b),  ev[0],  ev[1]);
        red_v2((float*)(g_agg2 + (size_t)src * B_ + b), -ev[0], -ev[1]);
    }
}

// ---- node MLP: templated half so ALL constant offsets are compile-time ----
template <int OBASE>
__device__ __forceinline__ void node_work(int idx, float* __restrict__ out)
{
    int n = idx >> 3;
    int b = idx & 7;

    float a[EOUT_];
    const float4* ag = g_agg4 + (size_t)n * (7 * B_) + b;
#pragma unroll
    for (int g = 0; g < 7; g++) {
        float4 v = ag[g * B_];
        a[4 * g + 0] = v.x; a[4 * g + 1] = v.y;
        a[4 * g + 2] = v.z; a[4 * g + 3] = v.w;
    }
    {
        float2 v = g_agg2[(size_t)n * B_ + b];
        a[28] = v.x; a[29] = v.y;
    }

    float* op = out + ((size_t)b * N_ + n) * NOUT_ + OBASE;
#pragma unroll
    for (int o = 0; o < 32; o += 8) {
        float acc[8];
#pragma unroll
        for (int t2 = 0; t2 < 8; t2++) acc[t2] = c_p.bn[OBASE + o + t2];
#pragma unroll
        for (int j = 0; j < EOUT_; j++) {
            float aj = a[j];
#pragma unroll
            for (int t2 = 0; t2 < 8; t2++)
                acc[t2] = fmaf(aj, c_p.Wn[j * NOUT_ + OBASE + o + t2], acc[t2]);
        }
        sig4(acc[0], acc[1], acc[2], acc[3]);
        sig4(acc[4], acc[5], acc[6], acc[7]);
        *(float4*)(op + o)     = make_float4(acc[0], acc[1], acc[2], acc[3]);
        *(float4*)(op + o + 4) = make_float4(acc[4], acc[5], acc[6], acc[7]);
    }
}

__global__ void __launch_bounds__(256) node_kernel(float* __restrict__ out)
{
    int t = blockIdx.x * blockDim.x + threadIdx.x;
    if (t >= BN_ * 2) return;
    if (t < BN_) {
        node_work<0>(t, out);          // uniform branch; BN_ % 32 == 0
    } else {
        node_work<32>(t - BN_, out);
    }
}

// ---------------- launch ----------------
extern "C" void kernel_launch(void* const* d_in, const int* in_sizes, int n_in,
                              void* d_out, int out_size) {
    const float* x  = (const float*)d_in[0];
    const int*   ei = (const int*)d_in[1];
    const float* ea = (const float*)d_in[2];
    const float* wm = (const float*)d_in[3];
    const float* ws = (const float*)d_in[4];
    const float* W1 = (const float*)d_in[5];
    const float* b1 = (const float*)d_in[6];
    const float* W2 = (const float*)d_in[7];
    const float* b2 = (const float*)d_in[8];
    const float* Wn = (const float*)d_in[9];
    const float* bn = (const float*)d_in[10];
    float* out = (float*)d_out;

    // zero agg + pack weights + edge_attr stats + finalize, all in one kernel
    prep_kernel<<<ZGRID_, 256>>>(W1, b1, W2, b2, Wn, bn, wm, ws, ea);

    // single constant-bank staging copy (D2D, capturable)
    void* p = nullptr;
    cudaGetSymbolAddress(&p, g_pack);
    cudaMemcpyToSymbolAsync(c_p, p, sizeof(Pack), 0,
                            cudaMemcpyDeviceToDevice, 0);

    proj_kernel<<<(BN_ + 255) / 256, 256>>>(x);
    edge_kernel<<<(E_ * B_) / 256, 256>>>(ei, ea);
    node_kernel<<<(BN_ * 2 + 255) / 256, 256>>>(out);
}

// round 17
// speedup vs baseline: 1.5385x; 1.0010x over previous
#include <cuda_runtime.h>
#include <math.h>

#define B_     8
#define N_     10000
#define D_     16
#define E_     320000
#define EH_    32
#define EOUT_  30
#define NOUT_  64
#define BN_    (B_ * N_)
#define ZGRID_ 512

typedef unsigned long long ull;

// ---------------- packed constant block (one D2D memcpy) ----------------
struct Pack {
    float W1[35 * EH_];      // layer-1 weights (edge uses rows 32..34)
    float b1[EH_];
    float W2t[EOUT_ * EH_];  // transposed layer-2 [30][32]
    float b2[EOUT_];
    float Wn[EOUT_ * NOUT_];
    float bn[NOUT_];
    float wind[4];           // wm0, wm1, ws0, ws1
    float norm[4];           // mean0, mean1, rstd0, rstd1
};
__constant__ Pack c_p;
__device__ Pack g_pack;     // staged by prep_kernel

// ---------------- device scratch ----------------
__device__ double g_part[ZGRID_ * 4];
__device__ unsigned g_counter = 0;
__device__ __align__(16) float4 g_ys4[N_ * 8 * B_];    // [n][q][b]: b1 + W1s.x
__device__ __align__(16) float4 g_yt4[N_ * 8 * B_];    // [n][q][b]: W1t.x
__device__ __align__(8)  float2 g_wind2[N_ * B_];      // [n][b]: (speed, dir)
__device__ __align__(16) float4 g_agg4[N_ * 7 * B_];   // [n][g][b]
__device__ __align__(8)  float2 g_agg2[N_ * B_];       // [n][b], outputs 28..29

// 4 sigmoids with ONE reciprocal (5 MUFU instead of 8)
__device__ __forceinline__ void sig4(float& a, float& b, float& c, float& d) {
    float pa = 1.0f + __expf(-a);
    float pb = 1.0f + __expf(-b);
    float pc = 1.0f + __expf(-c);
    float pd = 1.0f + __expf(-d);
    float pab = pa * pb, pcd = pc * pd;
    float r;
    asm("rcp.approx.f32 %0, %1;" : "=f"(r) : "f"(pab * pcd));
    float rab = r * pcd, rcd = r * pab;
    a = rab * pb; b = rab * pa; c = rcd * pd; d = rcd * pc;
}
__device__ __forceinline__ void sig2(float& a, float& b) {
    float pa = 1.0f + __expf(-a);
    float pb = 1.0f + __expf(-b);
    float r;
    asm("rcp.approx.f32 %0, %1;" : "=f"(r) : "f"(pa * pb));
    a = r * pb; b = r * pa;
}

__device__ __forceinline__ ull pack_f2(float lo, float hi) {
    ull r;
    asm("mov.b64 %0, {%1, %2};" : "=l"(r) : "f"(lo), "f"(hi));
    return r;
}
__device__ __forceinline__ void unpack_f2(ull v, float& lo, float& hi) {
    asm("mov.b64 {%0, %1}, %2;" : "=f"(lo), "=f"(hi) : "l"(v));
}
__device__ __forceinline__ ull fma_f2(ull a, ull b, ull c) {
    ull d;
    asm("fma.rn.f32x2 %0, %1, %2, %3;" : "=l"(d) : "l"(a), "l"(b), "l"(c));
    return d;
}
__device__ __forceinline__ ull add_f2(ull a, ull b) {
    ull d;
    asm("add.rn.f32x2 %0, %1, %2;" : "=l"(d) : "l"(a), "l"(b));
    return d;
}
__device__ __forceinline__ void red_v4(float* p, float a, float b, float c, float d) {
    asm volatile("red.global.add.v4.f32 [%0], {%1, %2, %3, %4};"
                 :: "l"(p), "f"(a), "f"(b), "f"(c), "f"(d) : "memory");
}
__device__ __forceinline__ void red_v2(float* p, float a, float b) {
    asm volatile("red.global.add.v2.f32 [%0], {%1, %2};"
                 :: "l"(p), "f"(a), "f"(b) : "memory");
}

// ---- prep: zero agg + pack weights + stats + finalize + PER-NODE PROJECTIONS ----
__global__ void __launch_bounds__(256) prep_kernel(
    const float* __restrict__ W1, const float* __restrict__ b1,
    const float* __restrict__ W2, const float* __restrict__ b2,
    const float* __restrict__ Wn, const float* __restrict__ bn,
    const float* __restrict__ wm, const float* __restrict__ ws,
    const float* __restrict__ ea, const float* __restrict__ x)
{
    __shared__ __align__(16) float sW1[35 * EH_];
    __shared__ float sb1[EH_];
    for (int i = threadIdx.x; i < 35 * EH_; i += blockDim.x) sW1[i] = W1[i];
    if (threadIdx.x < EH_) sb1[threadIdx.x] = b1[threadIdx.x];

    // 1) zero aggregates (no sync needed yet)
    float4 z4 = make_float4(0.f, 0.f, 0.f, 0.f);
    for (int i = blockIdx.x * blockDim.x + threadIdx.x; i < N_ * 7 * B_;
         i += gridDim.x * blockDim.x) {
        g_agg4[i] = z4;
    }
    for (int i = blockIdx.x * blockDim.x + threadIdx.x; i < N_ * B_;
         i += gridDim.x * blockDim.x) {
        g_agg2[i] = make_float2(0.f, 0.f);
    }
    // 2) pack weights (block 0)
    if (blockIdx.x == 0) {
        for (int i = threadIdx.x; i < 35 * EH_; i += blockDim.x)
            g_pack.W1[i] = W1[i];
        for (int i = threadIdx.x; i < EH_ * EOUT_; i += blockDim.x) {
            int j = i / EOUT_;
            int o = i % EOUT_;
            g_pack.W2t[o * EH_ + j] = W2[i];
        }
        for (int i = threadIdx.x; i < EOUT_ * NOUT_; i += blockDim.x)
            g_pack.Wn[i] = Wn[i];
        if (threadIdx.x < EH_)   g_pack.b1[threadIdx.x] = b1[threadIdx.x];
        if (threadIdx.x < EOUT_) g_pack.b2[threadIdx.x] = b2[threadIdx.x];
        if (threadIdx.x < NOUT_) g_pack.bn[threadIdx.x] = bn[threadIdx.x];
        if (threadIdx.x < 2) {
            g_pack.wind[threadIdx.x]     = wm[threadIdx.x];
            g_pack.wind[2 + threadIdx.x] = ws[threadIdx.x];
        }
    }

    // 3) per-node projections (threads t < BN_), weights from shared
    __syncthreads();
    {
        int t = blockIdx.x * blockDim.x + threadIdx.x;
        if (t < BN_) {
            int n = t >> 3;
            int b = t & 7;
            float xv[D_];
            const float4* px = (const float4*)(x + ((size_t)b * N_ + n) * D_);
#pragma unroll
            for (int q = 0; q < 4; q++) {
                float4 v = px[q];
                xv[4 * q + 0] = v.x; xv[4 * q + 1] = v.y;
                xv[4 * q + 2] = v.z; xv[4 * q + 3] = v.w;
            }
            float y[EH_];
#pragma unroll
            for (int j = 0; j < EH_; j++) y[j] = sb1[j];
#pragma unroll
            for (int k = 0; k < D_; k++) {
                float f = xv[k];
#pragma unroll
                for (int j = 0; j < EH_; j++)
                    y[j] = fmaf(f, sW1[k * EH_ + j], y[j]);
            }
            float4* ys = g_ys4 + (size_t)n * (8 * B_) + b;
#pragma unroll
            for (int q = 0; q < 8; q++)
                ys[q * B_] = make_float4(y[4 * q], y[4 * q + 1],
                                         y[4 * q + 2], y[4 * q + 3]);
#pragma unroll
            for (int j = 0; j < EH_; j++) y[j] = 0.0f;
#pragma unroll
            for (int k = 0; k < D_; k++) {
                float f = xv[k];
#pragma unroll
                for (int j = 0; j < EH_; j++)
                    y[j] = fmaf(f, sW1[(D_ + k) * EH_ + j], y[j]);
            }
            float4* yt = g_yt4 + (size_t)n * (8 * B_) + b;
#pragma unroll
            for (int q = 0; q < 8; q++)
                yt[q * B_] = make_float4(y[4 * q], y[4 * q + 1],
                                         y[4 * q + 2], y[4 * q + 3]);

            g_wind2[(size_t)n * B_ + b] =
                make_float2(fmaf(xv[14], ws[0], wm[0]),
                            fmaf(xv[15], ws[1], wm[1]));
        }
    }

    // 4) stats over edge_attr (double precision)
    double s0 = 0.0, s1 = 0.0, q0 = 0.0, q1 = 0.0;
    for (int i = blockIdx.x * blockDim.x + threadIdx.x; i < E_;
         i += gridDim.x * blockDim.x) {
        float a = ea[2 * i];
        float b = ea[2 * i + 1];
        s0 += (double)a;
        s1 += (double)b;
        q0 += (double)a * (double)a;
        q1 += (double)b * (double)b;
    }
    __shared__ double sh[4][8];
    for (int o = 16; o > 0; o >>= 1) {
        s0 += __shfl_down_sync(0xffffffffu, s0, o);
        s1 += __shfl_down_sync(0xffffffffu, s1, o);
        q0 += __shfl_down_sync(0xffffffffu, q0, o);
        q1 += __shfl_down_sync(0xffffffffu, q1, o);
    }
    int wid = threadIdx.x >> 5;
    if ((threadIdx.x & 31) == 0) {
        sh[0][wid] = s0; sh[1][wid] = s1; sh[2][wid] = q0; sh[3][wid] = q1;
    }
    __syncthreads();
    if (threadIdx.x == 0) {
        double t0 = 0, t1 = 0, t2 = 0, t3 = 0;
        for (int w = 0; w < 8; w++) {
            t0 += sh[0][w]; t1 += sh[1][w]; t2 += sh[2][w]; t3 += sh[3][w];
        }
        g_part[blockIdx.x * 4 + 0] = t0;
        g_part[blockIdx.x * 4 + 1] = t1;
        g_part[blockIdx.x * 4 + 2] = t2;
        g_part[blockIdx.x * 4 + 3] = t3;
    }
    // 5) last-block finalize -> g_pack.norm
    __shared__ bool isLast;
    __threadfence();
    if (threadIdx.x == 0) {
        unsigned old = atomicAdd(&g_counter, 1u);
        isLast = (old == gridDim.x - 1);
    }
    __syncthreads();
    if (isLast) {
        double t[4] = {0, 0, 0, 0};
        for (int i = threadIdx.x; i < (int)gridDim.x; i += blockDim.x) {
            t[0] += g_part[i * 4 + 0];
            t[1] += g_part[i * 4 + 1];
            t[2] += g_part[i * 4 + 2];
            t[3] += g_part[i * 4 + 3];
        }
        for (int c = 0; c < 4; c++) {
            for (int o = 16; o > 0; o >>= 1)
                t[c] += __shfl_down_sync(0xffffffffu, t[c], o);
            if ((threadIdx.x & 31) == 0) sh[c][wid] = t[c];
        }
        __syncthreads();
        if (threadIdx.x == 0) {
            double u0 = 0, u1 = 0, u2 = 0, u3 = 0;
            for (int w = 0; w < 8; w++) {
                u0 += sh[0][w]; u1 += sh[1][w]; u2 += sh[2][w]; u3 += sh[3][w];
            }
            const double n = (double)E_;
            double v0 = (u2 - u0 * u0 / n) / (n - 1.0);
            double v1 = (u3 - u1 * u1 / n) / (n - 1.0);
            g_pack.norm[0] = (float)(u0 / n);
            g_pack.norm[1] = (float)(u1 / n);
            g_pack.norm[2] = (float)(1.0 / sqrt(v0));
            g_pack.norm[3] = (float)(1.0 / sqrt(v1));
            g_counter = 0;   // reset for next graph replay
        }
    }
}

// ---------------- edge kernel: assemble h, layer 2 (const W2t), scatter ----------
__global__ void __launch_bounds__(256, 4) edge_kernel(
    const int* __restrict__ ei, const float* __restrict__ ea)
{
    unsigned gid = blockIdx.x * blockDim.x + threadIdx.x;
    if (gid >= (unsigned)(E_) * B_) return;
    int e = gid >> 3;       // edge id (8 consecutive lanes share it)
    int b = gid & 7;        // batch id
    int src = ei[e];
    int tgt = ei[E_ + e];

    float cd   = ea[2 * e];
    float cdi  = ea[2 * e + 1];
    float ean0 = (cd  - c_p.norm[0]) * c_p.norm[2];
    float ean1 = (cdi - c_p.norm[1]) * c_p.norm[3];

    float2 wd  = g_wind2[(size_t)src * B_ + b];
    float theta = fabsf(cdi - wd.y);
    float ewt   = fmaxf(0.0f, 3.0f * wd.x * __cosf(theta) / cd);

    // ---- layer-1 assembly: h = ys[src] + yt[tgt] + ean0*w32 + ean1*w33 + ewt*w34
    const ulonglong2* ys2 = (const ulonglong2*)(g_ys4 + (size_t)src * (8 * B_) + b);
    const ulonglong2* yt2 = (const ulonglong2*)(g_yt4 + (size_t)tgt * (8 * B_) + b);
    const ulonglong2* w32 = (const ulonglong2*)(c_p.W1 + 32 * EH_);
    const ulonglong2* w33 = (const ulonglong2*)(c_p.W1 + 33 * EH_);
    const ulonglong2* w34 = (const ulonglong2*)(c_p.W1 + 34 * EH_);
    ull e02 = pack_f2(ean0, ean0);
    ull e12 = pack_f2(ean1, ean1);
    ull ew2 = pack_f2(ewt,  ewt);

    ull h2[16];
#pragma unroll
    for (int q = 0; q < 8; q++) {
        ulonglong2 av = ys2[q * B_];
        ulonglong2 cv = yt2[q * B_];
        ulonglong2 v0 = w32[q];
        ulonglong2 v1 = w33[q];
        ulonglong2 v2 = w34[q];
        ull lo = add_f2(av.x, cv.x);
        ull hi = add_f2(av.y, cv.y);
        lo = fma_f2(e02, v0.x, lo);
        hi = fma_f2(e02, v0.y, hi);
        lo = fma_f2(e12, v1.x, lo);
        hi = fma_f2(e12, v1.y, hi);
        lo = fma_f2(ew2, v2.x, lo);
        hi = fma_f2(ew2, v2.y, hi);
        h2[2 * q]     = lo;
        h2[2 * q + 1] = hi;
    }
    // sigmoid (4 at a time, shared reciprocal)
#pragma unroll
    for (int q = 0; q < 8; q++) {
        float a0, a1, a2, a3;
        unpack_f2(h2[2 * q],     a0, a1);
        unpack_f2(h2[2 * q + 1], a2, a3);
        sig4(a0, a1, a2, a3);
        h2[2 * q]     = pack_f2(a0, a1);
        h2[2 * q + 1] = pack_f2(a2, a3);
    }

    // ---- layer 2: weights from CONSTANT (uniform port), coalesced reductions ----
    float4* at4 = g_agg4 + (size_t)tgt * (7 * B_) + b;
    float4* as4 = g_agg4 + (size_t)src * (7 * B_) + b;
#pragma unroll
    for (int g = 0; g < 7; g++) {
        int o0 = 4 * g;
        float ev[4];
#pragma unroll
        for (int t = 0; t < 4; t++) {
            ull acc2 = pack_f2(c_p.b2[o0 + t], 0.0f);
            const ulonglong2* w = (const ulonglong2*)(c_p.W2t + (o0 + t) * EH_);
#pragma unroll
            for (int p = 0; p < 8; p++) {
                ulonglong2 wv = w[p];
                acc2 = fma_f2(h2[2 * p],     wv.x, acc2);
                acc2 = fma_f2(h2[2 * p + 1], wv.y, acc2);
            }
            float lo, hi;
            unpack_f2(acc2, lo, hi);
            ev[t] = lo + hi;
        }
        sig4(ev[0], ev[1], ev[2], ev[3]);
        red_v4((float*)(at4 + g * B_),  ev[0],  ev[1],  ev[2],  ev[3]);
        red_v4((float*)(as4 + g * B_), -ev[0], -ev[1], -ev[2], -ev[3]);
    }
    // outputs 28, 29 -> float2 region
    {
        float ev[2];
#pragma unroll
        for (int t = 0; t < 2; t++) {
            ull acc2 = pack_f2(c_p.b2[28 + t], 0.0f);
            const ulonglong2* w = (const ulonglong2*)(c_p.W2t + (28 + t) * EH_);
#pragma unroll
            for (int p = 0; p < 8; p++) {
                ulonglong2 wv = w[p];
                acc2 = fma_f2(h2[2 * p],     wv.x, acc2);
                acc2 = fma_f2(h2[2 * p + 1], wv.y, acc2);
            }
            float lo, hi;
            unpack_f2(acc2, lo, hi);
            ev[t] = lo + hi;
        }
        sig2(ev[0], ev[1]);
        red_v2((float*)(g_agg2 + (size_t)tgt * B_ + b),  ev[0],  ev[1]);
        red_v2((float*)(g_agg2 + (size_t)src * B_ + b), -ev[0], -ev[1]);
    }
}

// ---- node MLP: templated half so ALL constant offsets are compile-time ----
template <int OBASE>
__device__ __forceinline__ void node_work(int idx, float* __restrict__ out)
{
    int n = idx >> 3;
    int b = idx & 7;

    float a[EOUT_];
    const float4* ag = g_agg4 + (size_t)n * (7 * B_) + b;
#pragma unroll
    for (int g = 0; g < 7; g++) {
        float4 v = ag[g * B_];
        a[4 * g + 0] = v.x; a[4 * g + 1] = v.y;
        a[4 * g + 2] = v.z; a[4 * g + 3] = v.w;
    }
    {
        float2 v = g_agg2[(size_t)n * B_ + b];
        a[28] = v.x; a[29] = v.y;
    }

    float* op = out + ((size_t)b * N_ + n) * NOUT_ + OBASE;
#pragma unroll
    for (int o = 0; o < 32; o += 8) {
        float acc[8];
#pragma unroll
        for (int t2 = 0; t2 < 8; t2++) acc[t2] = c_p.bn[OBASE + o + t2];
#pragma unroll
        for (int j = 0; j < EOUT_; j++) {
            float aj = a[j];
#pragma unroll
            for (int t2 = 0; t2 < 8; t2++)
                acc[t2] = fmaf(aj, c_p.Wn[j * NOUT_ + OBASE + o + t2], acc[t2]);
        }
        sig4(acc[0], acc[1], acc[2], acc[3]);
        sig4(acc[4], acc[5], acc[6], acc[7]);
        *(float4*)(op + o)     = make_float4(acc[0], acc[1], acc[2], acc[3]);
        *(float4*)(op + o + 4) = make_float4(acc[4], acc[5], acc[6], acc[7]);
    }
}

__global__ void __launch_bounds__(256) node_kernel(float* __restrict__ out)
{
    int t = blockIdx.x * blockDim.x + threadIdx.x;
    if (t >= BN_ * 2) return;
    if (t < BN_) {
        node_work<0>(t, out);          // uniform branch; BN_ % 32 == 0
    } else {
        node_work<32>(t - BN_, out);
    }
}

// ---------------- launch ----------------
extern "C" void kernel_launch(void* const* d_in, const int* in_sizes, int n_in,
                              void* d_out, int out_size) {
    const float* x  = (const float*)d_in[0];
    const int*   ei = (const int*)d_in[1];
    const float* ea = (const float*)d_in[2];
    const float* wm = (const float*)d_in[3];
    const float* ws = (const float*)d_in[4];
    const float* W1 = (const float*)d_in[5];
    const float* b1 = (const float*)d_in[6];
    const float* W2 = (const float*)d_in[7];
    const float* b2 = (const float*)d_in[8];
    const float* Wn = (const float*)d_in[9];
    const float* bn = (const float*)d_in[10];
    float* out = (float*)d_out;

    // zero agg + pack weights + stats + finalize + per-node projections
    prep_kernel<<<ZGRID_, 256>>>(W1, b1, W2, b2, Wn, bn, wm, ws, ea, x);

    // single constant-bank staging copy (D2D, capturable)
    void* p = nullptr;
    cudaGetSymbolAddress(&p, g_pack);
    cudaMemcpyToSymbolAsync(c_p, p, sizeof(Pack), 0,
                            cudaMemcpyDeviceToDevice, 0);

    edge_kernel<<<(E_ * B_) / 256, 256>>>(ei, ea);
    node_kernel<<<(BN_ * 2 + 255) / 256, 256>>>(out);
}